// round 1
// baseline (speedup 1.0000x reference)
#include <cuda_runtime.h>
#include <cstdint>

// Problem constants (from reference)
#define NN 100000
#define NE 800000
#define FH 64
#define FO 16

// ---------------- scratch (device globals; no allocation allowed) ------------
__device__ int   g_is64;
__device__ int   g_row[NE];
__device__ int   g_col[NE];
__device__ int   g_cnt[NN];
__device__ int   g_cur[NN];
__device__ int   g_off[NN];
__device__ float g_dinv[NN];
__device__ int   g_srcs[NE];
__device__ float g_nrm[NE];
__device__ float g_tmp1[(size_t)NN * FH];   // x @ W1
__device__ float g_h[(size_t)NN * FH];      // relu(agg1 + b1)
__device__ float g_tmp2[(size_t)NN * FO];   // h @ W2
__device__ int   g_partial[256];
__device__ int   g_pscan[256];

// ---------------- dtype detection + conversion ------------------------------
__global__ void k_detect(const void* edge, int n_nodes, int n_check) {
    int tid = threadIdx.x;
    if (tid == 0) g_is64 = 1;
    __syncthreads();
    const long long* p = (const long long*)edge;
    bool bad = false;
    for (int i = tid; i < n_check; i += blockDim.x) {
        long long v = p[i];
        if (v < 0 || v >= (long long)n_nodes) bad = true;
    }
    if (__syncthreads_or(bad ? 1 : 0)) {
        if (tid == 0) g_is64 = 0;
    }
}

__global__ void k_convert(const void* edge, int E) {
    int e = blockIdx.x * blockDim.x + threadIdx.x;
    if (e >= E) return;
    if (g_is64) {
        const long long* p = (const long long*)edge;
        g_row[e] = (int)p[e];
        g_col[e] = (int)p[e + E];
    } else {
        const int* p = (const int*)edge;
        g_row[e] = p[e];
        g_col[e] = p[e + E];
    }
}

// ---------------- degree / CSR build ----------------------------------------
__global__ void k_zero(int n) {
    int i = blockIdx.x * blockDim.x + threadIdx.x;
    if (i < n) { g_cnt[i] = 0; g_cur[i] = 0; }
}

__global__ void k_hist(int E) {
    int e = blockIdx.x * blockDim.x + threadIdx.x;
    if (e >= E) return;
    atomicAdd(&g_cnt[g_col[e]], 1);
}

__global__ void k_dinv(int n) {
    int i = blockIdx.x * blockDim.x + threadIdx.x;
    if (i < n) g_dinv[i] = rsqrtf((float)g_cnt[i] + 1.0f);  // +1 self loop
}

// 2-level exclusive scan of g_cnt -> g_off, chunk = 1024
__global__ void k_scanA(int n) {   // 256 threads; each block sums a 1024-chunk
    __shared__ int s[256];
    int b = blockIdx.x, t = threadIdx.x;
    int base = b * 1024;
    int acc = 0;
    for (int j = t; j < 1024; j += 256) {
        int i = base + j;
        acc += (i < n) ? g_cnt[i] : 0;
    }
    s[t] = acc;
    __syncthreads();
    for (int d = 128; d > 0; d >>= 1) {
        if (t < d) s[t] += s[t + d];
        __syncthreads();
    }
    if (t == 0) g_partial[b] = s[0];
}

__global__ void k_scanB(int nb) {  // <<<1,1>>> exclusive scan of partials
    int acc = 0;
    for (int j = 0; j < nb; j++) {
        int v = g_partial[j];
        g_pscan[j] = acc;
        acc += v;
    }
}

__global__ void k_scanC(int n) {   // 1024 threads, Hillis-Steele within chunk
    __shared__ int s[1024];
    int b = blockIdx.x, t = threadIdx.x;
    int i = b * 1024 + t;
    int val = (i < n) ? g_cnt[i] : 0;
    s[t] = val;
    __syncthreads();
    for (int d = 1; d < 1024; d <<= 1) {
        int add = (t >= d) ? s[t - d] : 0;
        __syncthreads();
        s[t] += add;
        __syncthreads();
    }
    if (i < n) g_off[i] = s[t] - val + g_pscan[b];
}

__global__ void k_scatter(int E) {
    int e = blockIdx.x * blockDim.x + threadIdx.x;
    if (e >= E) return;
    int c = g_col[e];
    int r = g_row[e];
    int p = g_off[c] + atomicAdd(&g_cur[c], 1);
    g_srcs[p] = r;
    g_nrm[p]  = g_dinv[r] * g_dinv[c];
}

// ---------------- dense GEMM: out[n, COLS] = A[n,64] @ W[64,COLS] ------------
template <int COLS>
__global__ void k_gemm64(const float* __restrict__ A,
                         const float* __restrict__ W,
                         float* __restrict__ out, int n) {
    __shared__ float Xs[64][65];       // padded: avoid stride-64 bank conflicts
    __shared__ float Ws[64][COLS];

    int tid  = threadIdx.x;            // 256 threads
    int base = blockIdx.x * 64;

    for (int i = tid; i < 64 * COLS; i += 256)
        Ws[i / COLS][i % COLS] = W[i];

    // load 64x64 tile of A via float4 (rows are 64 f32, 4-divisible)
    for (int i = tid; i < 1024; i += 256) {
        int off = i * 4;
        int r = off >> 6, k = off & 63;
        float4 v = make_float4(0.f, 0.f, 0.f, 0.f);
        int gr = base + r;
        if (gr < n) v = *(const float4*)(A + (size_t)gr * 64 + k);
        Xs[r][k]     = v.x;
        Xs[r][k + 1] = v.y;
        Xs[r][k + 2] = v.z;
        Xs[r][k + 3] = v.w;
    }
    __syncthreads();

    const int TPR  = 4;                // 4 threads per row
    const int CPT  = COLS / TPR;       // cols per thread
    int rr   = tid / TPR;
    int cseg = (tid % TPR) * CPT;

    float acc[CPT];
#pragma unroll
    for (int j = 0; j < CPT; j++) acc[j] = 0.f;

#pragma unroll 8
    for (int k = 0; k < 64; k++) {
        float a = Xs[rr][k];
#pragma unroll
        for (int j = 0; j < CPT; j++) acc[j] += a * Ws[k][cseg + j];
    }

    int gr = base + rr;
    if (gr < n) {
#pragma unroll
        for (int j = 0; j < CPT; j++)
            out[(size_t)gr * COLS + cseg + j] = acc[j];
    }
}

// ---------------- aggregation ------------------------------------------------
// Layer 1: h[i] = relu( b1 + dinv[i]^2*tmp[i] + sum_e nrm*tmp[src] ), F=64.
// One warp per node; lane handles features {lane, lane+32}.
__global__ void k_agg1(const float* __restrict__ tmp,
                       const float* __restrict__ b1,
                       float* __restrict__ h, int n) {
    int warp = (blockIdx.x * blockDim.x + threadIdx.x) >> 5;
    int lane = threadIdx.x & 31;
    if (warp >= n) return;
    int i = warp;
    float ws = g_dinv[i] * g_dinv[i];
    const float* ti = tmp + (size_t)i * 64;
    float a0 = ti[lane]      * ws;
    float a1 = ti[lane + 32] * ws;
    int e0 = g_off[i], e1 = e0 + g_cnt[i];
    for (int e = e0; e < e1; e++) {
        int s  = g_srcs[e];
        float w = g_nrm[e];
        const float* ts = tmp + (size_t)s * 64;
        a0 += ts[lane]      * w;
        a1 += ts[lane + 32] * w;
    }
    h[(size_t)i * 64 + lane]      = fmaxf(a0 + b1[lane], 0.f);
    h[(size_t)i * 64 + lane + 32] = fmaxf(a1 + b1[lane + 32], 0.f);
}

// Layer 2: out[i] = b2 + dinv^2*tmp2[i] + sum nrm*tmp2[src], F=16.
// 16 threads per node (2 nodes per warp).
__global__ void k_agg2(const float* __restrict__ tmp,
                       const float* __restrict__ b2,
                       float* __restrict__ out, int n) {
    int g = (blockIdx.x * blockDim.x + threadIdx.x) >> 4;
    int l = threadIdx.x & 15;
    if (g >= n) return;
    float ws = g_dinv[g] * g_dinv[g];
    float a = tmp[(size_t)g * 16 + l] * ws;
    int e0 = g_off[g], e1 = e0 + g_cnt[g];
    for (int e = e0; e < e1; e++) {
        int s  = g_srcs[e];
        float w = g_nrm[e];
        a += tmp[(size_t)s * 16 + l] * w;
    }
    out[(size_t)g * 16 + l] = a + b2[l];
}

// ---------------- launcher ---------------------------------------------------
extern "C" void kernel_launch(void* const* d_in, const int* in_sizes, int n_in,
                              void* d_out, int out_size) {
    const float* x  = (const float*)d_in[0];
    const void*  ei = d_in[1];                 // int64 or int32, detected on device
    const float* W1 = (const float*)d_in[2];
    const float* b1 = (const float*)d_in[3];
    const float* W2 = (const float*)d_in[4];
    const float* b2 = (const float*)d_in[5];
    float* out = (float*)d_out;

    const int n = in_sizes[0] / FH;            // 100000
    const int E = in_sizes[1] / 2;             // 800000

    float* tmp1; cudaGetSymbolAddress((void**)&tmp1, g_tmp1);
    float* h;    cudaGetSymbolAddress((void**)&h,    g_h);
    float* tmp2; cudaGetSymbolAddress((void**)&tmp2, g_tmp2);

    const int T = 256;
    const int gE = (E + T - 1) / T;
    const int gN = (n + T - 1) / T;
    const int nb = (n + 1023) / 1024;

    k_detect <<<1, 256>>>(ei, n, 2048);
    k_convert<<<gE, T>>>(ei, E);
    k_zero   <<<gN, T>>>(n);
    k_hist   <<<gE, T>>>(E);
    k_dinv   <<<gN, T>>>(n);
    k_scanA  <<<nb, 256>>>(n);
    k_scanB  <<<1, 1>>>(nb);
    k_scanC  <<<nb, 1024>>>(n);
    k_scatter<<<gE, T>>>(E);

    // Layer 1
    k_gemm64<64><<<(n + 63) / 64, 256>>>(x, W1, tmp1, n);
    k_agg1      <<<(n * 32 + T - 1) / T, T>>>(tmp1, b1, h, n);

    // Layer 2
    k_gemm64<16><<<(n + 63) / 64, 256>>>(h, W2, tmp2, n);
    k_agg2      <<<(n * 16 + T - 1) / T, T>>>(tmp2, b2, out, n);

    (void)n_in; (void)out_size;
}

// round 2
// speedup vs baseline: 1.6944x; 1.6944x over previous
#include <cuda_runtime.h>
#include <cstdint>

#define NN 100000
#define NE 800000
#define FH 64
#define FO 16

// ---------------- scratch ----------------------------------------------------
__device__ int   g_is64;
__device__ int2  g_rc[NE];                  // (row=src, col=dst) per input edge
__device__ int   g_cnt[NN];                 // in-degree (no self loop)
__device__ int   g_off[NN];                 // CSR offsets; AFTER scatter = end ptr
__device__ float g_dinv[NN];
__device__ int2  g_sn[NE];                  // CSR payload: (src, nrm bits)
__device__ float g_tmp1[(size_t)NN * FH];
__device__ float g_h[(size_t)NN * FH];
__device__ float g_tmp2[(size_t)NN * FO];
__device__ int   g_partial[128];
__device__ int   g_pscan[128];

// ---------------- dtype detect ----------------------------------------------
__global__ void k_detect(const void* edge, int n_nodes, int n_check) {
    int tid = threadIdx.x;
    const long long* p = (const long long*)edge;
    bool bad = false;
    for (int i = tid; i < n_check; i += blockDim.x) {
        long long v = p[i];
        if (v < 0 || v >= (long long)n_nodes) bad = true;
    }
    int anybad = __syncthreads_or(bad ? 1 : 0);
    if (tid == 0) g_is64 = anybad ? 0 : 1;
}

// ---------------- convert + histogram (fused) --------------------------------
__global__ void k_conv_hist(const void* edge, int E) {
    int e = blockIdx.x * blockDim.x + threadIdx.x;
    if (e >= E) return;
    int r, c;
    if (g_is64) {
        const long long* p = (const long long*)edge;
        r = (int)p[e]; c = (int)p[e + E];
    } else {
        const int* p = (const int*)edge;
        r = p[e]; c = p[e + E];
    }
    g_rc[e] = make_int2(r, c);
    atomicAdd(&g_cnt[c], 1);
}

// ---------------- scan level A: block sums + fused dinv ----------------------
__global__ void k_scanA(int n) {
    __shared__ int s[256];
    int b = blockIdx.x, t = threadIdx.x;
    int base = b * 1024;
    int acc = 0;
    for (int j = t; j < 1024; j += 256) {
        int i = base + j;
        if (i < n) {
            int c = g_cnt[i];
            acc += c;
            g_dinv[i] = rsqrtf((float)c + 1.0f);   // +1 self loop
        }
    }
    s[t] = acc;
    __syncthreads();
    for (int d = 128; d > 0; d >>= 1) {
        if (t < d) s[t] += s[t + d];
        __syncthreads();
    }
    if (t == 0) g_partial[b] = s[0];
}

// ---------------- scan level B: single block over <=128 partials -------------
__global__ void k_scanB(int nb) {
    __shared__ int s[128];
    int t = threadIdx.x;
    int v = (t < nb) ? g_partial[t] : 0;
    s[t] = v;
    __syncthreads();
    for (int d = 1; d < 128; d <<= 1) {
        int add = (t >= d) ? s[t - d] : 0;
        __syncthreads();
        s[t] += add;
        __syncthreads();
    }
    if (t < nb) g_pscan[t] = s[t] - v;       // exclusive
}

// ---------------- scan level C: per-chunk scan -------------------------------
__global__ void k_scanC(int n) {
    __shared__ int s[1024];
    int b = blockIdx.x, t = threadIdx.x;
    int i = b * 1024 + t;
    int val = (i < n) ? g_cnt[i] : 0;
    s[t] = val;
    __syncthreads();
    for (int d = 1; d < 1024; d <<= 1) {
        int add = (t >= d) ? s[t - d] : 0;
        __syncthreads();
        s[t] += add;
        __syncthreads();
    }
    if (i < n) g_off[i] = s[t] - val + g_pscan[b];
}

// ---------------- counting-sort scatter (mutates g_off -> end pointers) ------
__global__ void k_scatter(int E) {
    int e = blockIdx.x * blockDim.x + threadIdx.x;
    if (e >= E) return;
    int2 rc = g_rc[e];
    float nr = g_dinv[rc.x] * g_dinv[rc.y];
    int p = atomicAdd(&g_off[rc.y], 1);
    g_sn[p] = make_int2(rc.x, __float_as_int(nr));
}

// ---------------- GEMM: out[n,COLS] = A[n,64] @ W[64,COLS], 4x4 reg blocking -
template <int COLS>
__global__ void k_gemm(const float* __restrict__ A,
                       const float* __restrict__ W,
                       float* __restrict__ out, int n) {
    // block tile: 64 rows x COLS cols; threads = (COLS/4) * 16
    constexpr int TX = COLS / 4;            // threads along cols
    constexpr int NT = TX * 16;
    __shared__ float XsT[64][68];           // [k][row], pad 4 (68*4B % 16 == 0)
    __shared__ float Ws[64 * COLS];         // [k][c] flat

    int tid  = threadIdx.x;
    int base = blockIdx.x * 64;

    // load W (contiguous float4)
    for (int i = tid; i < 64 * COLS / 4; i += NT)
        ((float4*)Ws)[i] = ((const float4*)W)[i];

    // load A tile transposed: i indexes (row, k4)
    for (int i = tid; i < 64 * 16; i += NT) {
        int r  = i >> 4;
        int k4 = (i & 15) << 2;
        float4 v = make_float4(0.f, 0.f, 0.f, 0.f);
        int gr = base + r;
        if (gr < n) v = *(const float4*)(A + (size_t)gr * 64 + k4);
        XsT[k4    ][r] = v.x;
        XsT[k4 + 1][r] = v.y;
        XsT[k4 + 2][r] = v.z;
        XsT[k4 + 3][r] = v.w;
    }
    __syncthreads();

    int tx = tid % TX, ty = tid / TX;
    int c0 = tx * 4,   r0 = ty * 4;

    float acc[4][4];
#pragma unroll
    for (int i = 0; i < 4; i++)
#pragma unroll
        for (int j = 0; j < 4; j++) acc[i][j] = 0.f;

#pragma unroll 4
    for (int k = 0; k < 64; k++) {
        float4 a = *(const float4*)&XsT[k][r0];
        float4 w = *(const float4*)&Ws[k * COLS + c0];
        acc[0][0] += a.x * w.x; acc[0][1] += a.x * w.y; acc[0][2] += a.x * w.z; acc[0][3] += a.x * w.w;
        acc[1][0] += a.y * w.x; acc[1][1] += a.y * w.y; acc[1][2] += a.y * w.z; acc[1][3] += a.y * w.w;
        acc[2][0] += a.z * w.x; acc[2][1] += a.z * w.y; acc[2][2] += a.z * w.z; acc[2][3] += a.z * w.w;
        acc[3][0] += a.w * w.x; acc[3][1] += a.w * w.y; acc[3][2] += a.w * w.z; acc[3][3] += a.w * w.w;
    }

#pragma unroll
    for (int i = 0; i < 4; i++) {
        int gr = base + r0 + i;
        if (gr < n)
            *(float4*)(out + (size_t)gr * COLS + c0) =
                make_float4(acc[i][0], acc[i][1], acc[i][2], acc[i][3]);
    }
}

// ---------------- aggregation, layer 1 (F=64): one warp per node -------------
__global__ void k_agg1(const float2* __restrict__ tmp,
                       const float2* __restrict__ b1,
                       float2* __restrict__ h, int n) {
    int i = (blockIdx.x * blockDim.x + threadIdx.x) >> 5;
    int lane = threadIdx.x & 31;
    if (i >= n) return;
    float di = g_dinv[i];
    float ws = di * di;
    float2 v = tmp[(size_t)i * 32 + lane];
    float a0 = v.x * ws, a1 = v.y * ws;

    int e1 = g_off[i];              // end (post-scatter)
    int e0 = e1 - g_cnt[i];
    int e = e0;
    for (; e + 2 <= e1; e += 2) {
        int2 q0 = g_sn[e];
        int2 q1 = g_sn[e + 1];
        float2 t0 = tmp[(size_t)q0.x * 32 + lane];
        float2 t1 = tmp[(size_t)q1.x * 32 + lane];
        float w0 = __int_as_float(q0.y);
        float w1 = __int_as_float(q1.y);
        a0 += t0.x * w0; a1 += t0.y * w0;
        a0 += t1.x * w1; a1 += t1.y * w1;
    }
    if (e < e1) {
        int2 q = g_sn[e];
        float2 t = tmp[(size_t)q.x * 32 + lane];
        float w = __int_as_float(q.y);
        a0 += t.x * w; a1 += t.y * w;
    }
    float2 bb = b1[lane];
    h[(size_t)i * 32 + lane] = make_float2(fmaxf(a0 + bb.x, 0.f),
                                           fmaxf(a1 + bb.y, 0.f));
}

// ---------------- aggregation, layer 2 (F=16): 16 threads per node -----------
__global__ void k_agg2(const float* __restrict__ tmp,
                       const float* __restrict__ b2,
                       float* __restrict__ out, int n) {
    int i = (blockIdx.x * blockDim.x + threadIdx.x) >> 4;
    int l = threadIdx.x & 15;
    if (i >= n) return;
    float di = g_dinv[i];
    float a = tmp[(size_t)i * 16 + l] * di * di;

    int e1 = g_off[i];
    int e0 = e1 - g_cnt[i];
    int e = e0;
    for (; e + 2 <= e1; e += 2) {
        int2 q0 = g_sn[e];
        int2 q1 = g_sn[e + 1];
        float t0 = tmp[(size_t)q0.x * 16 + l];
        float t1 = tmp[(size_t)q1.x * 16 + l];
        a += t0 * __int_as_float(q0.y);
        a += t1 * __int_as_float(q1.y);
    }
    if (e < e1) {
        int2 q = g_sn[e];
        a += tmp[(size_t)q.x * 16 + l] * __int_as_float(q.y);
    }
    out[(size_t)i * 16 + l] = a + b2[l];
}

// ---------------- launcher ---------------------------------------------------
extern "C" void kernel_launch(void* const* d_in, const int* in_sizes, int n_in,
                              void* d_out, int out_size) {
    const float* x  = (const float*)d_in[0];
    const void*  ei = d_in[1];
    const float* W1 = (const float*)d_in[2];
    const float* b1 = (const float*)d_in[3];
    const float* W2 = (const float*)d_in[4];
    const float* b2 = (const float*)d_in[5];
    float* out = (float*)d_out;

    const int n = in_sizes[0] / FH;
    const int E = in_sizes[1] / 2;

    float* tmp1; cudaGetSymbolAddress((void**)&tmp1, g_tmp1);
    float* h;    cudaGetSymbolAddress((void**)&h,    g_h);
    float* tmp2; cudaGetSymbolAddress((void**)&tmp2, g_tmp2);
    int*   cnt;  cudaGetSymbolAddress((void**)&cnt,  g_cnt);

    const int T = 256;
    const int gE = (E + T - 1) / T;
    const int nb = (n + 1023) / 1024;

    k_detect   <<<1, 256>>>(ei, n, 2048);
    cudaMemsetAsync(cnt, 0, (size_t)n * sizeof(int));
    k_conv_hist<<<gE, T>>>(ei, E);
    k_scanA    <<<nb, 256>>>(n);
    k_scanB    <<<1, 128>>>(nb);
    k_scanC    <<<nb, 1024>>>(n);
    k_scatter  <<<gE, T>>>(E);

    // Layer 1
    k_gemm<64><<<(n + 63) / 64, 256>>>(x, W1, tmp1, n);
    k_agg1    <<<(n * 32 + T - 1) / T, T>>>((const float2*)tmp1, (const float2*)b1,
                                            (float2*)h, n);
    // Layer 2
    k_gemm<16><<<(n + 63) / 64, 64>>>(h, W2, tmp2, n);
    k_agg2    <<<(n * 16 + T - 1) / T, T>>>(tmp2, b2, out, n);

    (void)n_in; (void)out_size;
}

// round 3
// speedup vs baseline: 1.9365x; 1.1429x over previous
#include <cuda_runtime.h>
#include <cstdint>

#define NN 100000
#define NE 800000
#define FH 64
#define FO 16
#define SCAN_T 1024

// ---------------- scratch ----------------------------------------------------
__device__ int   g_cnt[NN + 128];     // [0,NN): in-degree; [NN,NN+128): lookback slots
__device__ int   g_off[NN];           // CSR offsets; AFTER scatter = end pointers
__device__ float g_dinv[NN];
__device__ int2  g_sn[NE];            // CSR payload: (src, nrm bits)
__device__ float g_tmp1[(size_t)NN * FH];
__device__ float g_h[(size_t)NN * FH];
__device__ float g_tmp2[(size_t)NN * FO];

// ---------------- per-block dtype detect (must run with blockDim.x>=256) -----
__device__ __forceinline__ int block_detect64(const void* edge, int n_nodes) {
    const long long* p = (const long long*)edge;
    long long v = p[threadIdx.x & 255];     // first 2KB; in-bounds for either dtype
    bool bad = (v < 0 || v >= (long long)n_nodes);
    return __syncthreads_or(bad ? 1 : 0) ? 0 : 1;
}

// ---------------- histogram over destination column --------------------------
__global__ void k_hist(const void* edge, int E, int n_nodes) {
    int is64 = block_detect64(edge, n_nodes);
    int e = blockIdx.x * blockDim.x + threadIdx.x;
    if (e >= E) return;
    int c = is64 ? (int)((const long long*)edge)[e + E]
                 : ((const int*)edge)[e + E];
    atomicAdd(&g_cnt[c], 1);
}

// ---------------- fused scan (block scan + deadlock-free lookback) + dinv ----
__global__ void k_scan(int n) {
    __shared__ int s[SCAN_T];
    __shared__ int s_pref;
    int b = blockIdx.x, t = threadIdx.x;
    int i = b * SCAN_T + t;
    int val = 0;
    if (i < n) {
        val = g_cnt[i];
        g_dinv[i] = rsqrtf((float)val + 1.0f);   // +1 self loop
    }
    s[t] = val;
    __syncthreads();
    for (int d = 1; d < SCAN_T; d <<= 1) {
        int add = (t >= d) ? s[t - d] : 0;
        __syncthreads();
        s[t] += add;
        __syncthreads();
    }
    // publish own aggregate (+1 so 0 == not-ready). Publishing never blocks.
    if (t == SCAN_T - 1) atomicExch(&g_cnt[NN + b], s[t] + 1);
    if (t == 0) s_pref = 0;
    __syncthreads();
    if (t < b) {                                  // poll predecessors in parallel
        int v;
        do { v = atomicAdd(&g_cnt[NN + t], 0); } while (v == 0);
        atomicAdd(&s_pref, v - 1);
    }
    __syncthreads();
    if (i < n) g_off[i] = s[t] - val + s_pref;    // exclusive prefix
}

// ---------------- counting-sort scatter (mutates g_off -> end pointers) ------
__global__ void k_scatter(const void* edge, int E, int n_nodes) {
    int is64 = block_detect64(edge, n_nodes);
    int e = blockIdx.x * blockDim.x + threadIdx.x;
    if (e >= E) return;
    int r, c;
    if (is64) {
        const long long* p = (const long long*)edge;
        r = (int)p[e]; c = (int)p[e + E];
    } else {
        const int* p = (const int*)edge;
        r = p[e]; c = p[e + E];
    }
    float nr = g_dinv[r] * g_dinv[c];
    int pos = atomicAdd(&g_off[c], 1);
    g_sn[pos] = make_int2(r, __float_as_int(nr));
}

// ---------------- packed f32x2 helpers ---------------------------------------
__device__ __forceinline__ unsigned long long pack2(float v) {
    unsigned long long r;
    unsigned int u = __float_as_uint(v);
    asm("mov.b64 %0, {%1, %1};" : "=l"(r) : "r"(u));
    return r;
}
__device__ __forceinline__ void fma2(unsigned long long& d,
                                     unsigned long long a, unsigned long long b) {
    asm("fma.rn.f32x2 %0, %1, %2, %0;" : "+l"(d) : "l"(a), "l"(b));
}
__device__ __forceinline__ void unpack2(unsigned long long v, float& lo, float& hi) {
    unsigned int l, h;
    asm("mov.b64 {%0, %1}, %2;" : "=r"(l), "=r"(h) : "l"(v));
    lo = __uint_as_float(l); hi = __uint_as_float(h);
}

// ---------------- GEMM1: out[n,64] = A[n,64] @ W[64,64], packed f32x2 --------
// 128 threads; tile 64 rows x 64 cols; thread = 8 rows x 4 cols.
__global__ void k_gemm64(const float* __restrict__ A,
                         const float* __restrict__ W,
                         float* __restrict__ out, int n) {
    __shared__ float XsT[64][66];        // [k][row]; pad 66 (even => 8B-aligned pairs)
    __shared__ float Ws[64 * 64];

    int tid  = threadIdx.x;
    int base = blockIdx.x * 64;

    for (int i = tid; i < 64 * 16; i += 128)
        ((float4*)Ws)[i] = ((const float4*)W)[i];

    for (int i = tid; i < 64 * 16; i += 128) {
        int r  = i >> 4;
        int k4 = (i & 15) << 2;
        float4 v = make_float4(0.f, 0.f, 0.f, 0.f);
        int gr = base + r;
        if (gr < n) v = *(const float4*)(A + (size_t)gr * 64 + k4);
        XsT[k4    ][r] = v.x;
        XsT[k4 + 1][r] = v.y;
        XsT[k4 + 2][r] = v.z;
        XsT[k4 + 3][r] = v.w;
    }
    __syncthreads();

    int tx = tid & 15, ty = tid >> 4;
    int c0 = tx * 4,   r0 = ty * 8;

    unsigned long long acc[4][4];
#pragma unroll
    for (int p = 0; p < 4; p++)
#pragma unroll
        for (int j = 0; j < 4; j++) acc[p][j] = 0ull;

#pragma unroll 2
    for (int k = 0; k < 64; k++) {
        unsigned long long a0 = *(const unsigned long long*)&XsT[k][r0];
        unsigned long long a1 = *(const unsigned long long*)&XsT[k][r0 + 2];
        unsigned long long a2 = *(const unsigned long long*)&XsT[k][r0 + 4];
        unsigned long long a3 = *(const unsigned long long*)&XsT[k][r0 + 6];
        float4 w = *(const float4*)&Ws[k * 64 + c0];
        unsigned long long w0 = pack2(w.x), w1 = pack2(w.y),
                           w2 = pack2(w.z), w3 = pack2(w.w);
        fma2(acc[0][0], a0, w0); fma2(acc[0][1], a0, w1);
        fma2(acc[0][2], a0, w2); fma2(acc[0][3], a0, w3);
        fma2(acc[1][0], a1, w0); fma2(acc[1][1], a1, w1);
        fma2(acc[1][2], a1, w2); fma2(acc[1][3], a1, w3);
        fma2(acc[2][0], a2, w0); fma2(acc[2][1], a2, w1);
        fma2(acc[2][2], a2, w2); fma2(acc[2][3], a2, w3);
        fma2(acc[3][0], a3, w0); fma2(acc[3][1], a3, w1);
        fma2(acc[3][2], a3, w2); fma2(acc[3][3], a3, w3);
    }

#pragma unroll
    for (int p = 0; p < 4; p++) {
        float lo0, hi0, lo1, hi1, lo2, hi2, lo3, hi3;
        unpack2(acc[p][0], lo0, hi0);
        unpack2(acc[p][1], lo1, hi1);
        unpack2(acc[p][2], lo2, hi2);
        unpack2(acc[p][3], lo3, hi3);
        int gr = base + r0 + 2 * p;
        if (gr < n)
            *(float4*)(out + (size_t)gr * 64 + c0) = make_float4(lo0, lo1, lo2, lo3);
        if (gr + 1 < n)
            *(float4*)(out + (size_t)(gr + 1) * 64 + c0) = make_float4(hi0, hi1, hi2, hi3);
    }
}

// ---------------- GEMM2: out[n,16] = A[n,64] @ W[64,16], scalar 4x4 ----------
__global__ void k_gemm16(const float* __restrict__ A,
                         const float* __restrict__ W,
                         float* __restrict__ out, int n) {
    __shared__ float XsT[64][68];
    __shared__ float Ws[64 * 16];
    int tid  = threadIdx.x;                 // 64 threads
    int base = blockIdx.x * 64;

    for (int i = tid; i < 64 * 4; i += 64)
        ((float4*)Ws)[i] = ((const float4*)W)[i];
    for (int i = tid; i < 64 * 16; i += 64) {
        int r  = i >> 4;
        int k4 = (i & 15) << 2;
        float4 v = make_float4(0.f, 0.f, 0.f, 0.f);
        int gr = base + r;
        if (gr < n) v = *(const float4*)(A + (size_t)gr * 64 + k4);
        XsT[k4    ][r] = v.x;
        XsT[k4 + 1][r] = v.y;
        XsT[k4 + 2][r] = v.z;
        XsT[k4 + 3][r] = v.w;
    }
    __syncthreads();

    int tx = tid & 3, ty = tid >> 2;        // 4 cols-groups x 16 rows-groups
    int c0 = tx * 4,  r0 = ty * 4;

    float acc[4][4];
#pragma unroll
    for (int i = 0; i < 4; i++)
#pragma unroll
        for (int j = 0; j < 4; j++) acc[i][j] = 0.f;

#pragma unroll 4
    for (int k = 0; k < 64; k++) {
        float4 a = *(const float4*)&XsT[k][r0];
        float4 w = *(const float4*)&Ws[k * 16 + c0];
        acc[0][0] += a.x * w.x; acc[0][1] += a.x * w.y; acc[0][2] += a.x * w.z; acc[0][3] += a.x * w.w;
        acc[1][0] += a.y * w.x; acc[1][1] += a.y * w.y; acc[1][2] += a.y * w.z; acc[1][3] += a.y * w.w;
        acc[2][0] += a.z * w.x; acc[2][1] += a.z * w.y; acc[2][2] += a.z * w.z; acc[2][3] += a.z * w.w;
        acc[3][0] += a.w * w.x; acc[3][1] += a.w * w.y; acc[3][2] += a.w * w.z; acc[3][3] += a.w * w.w;
    }
#pragma unroll
    for (int i = 0; i < 4; i++) {
        int gr = base + r0 + i;
        if (gr < n)
            *(float4*)(out + (size_t)gr * 16 + c0) =
                make_float4(acc[i][0], acc[i][1], acc[i][2], acc[i][3]);
    }
}

// ---------------- aggregation, layer 1 (F=64): one warp per node, unroll 4 ---
__global__ void k_agg1(const float2* __restrict__ tmp,
                       const float2* __restrict__ b1,
                       float2* __restrict__ h, int n) {
    int i = (blockIdx.x * blockDim.x + threadIdx.x) >> 5;
    int lane = threadIdx.x & 31;
    if (i >= n) return;
    float di = g_dinv[i];
    float ws = di * di;
    float2 v = tmp[(size_t)i * 32 + lane];
    float a0 = v.x * ws, a1 = v.y * ws;

    int e1 = g_off[i];
    int e  = e1 - g_cnt[i];
    for (; e + 4 <= e1; e += 4) {
        int2 q0 = g_sn[e];
        int2 q1 = g_sn[e + 1];
        int2 q2 = g_sn[e + 2];
        int2 q3 = g_sn[e + 3];
        float2 t0 = tmp[(size_t)q0.x * 32 + lane];
        float2 t1 = tmp[(size_t)q1.x * 32 + lane];
        float2 t2 = tmp[(size_t)q2.x * 32 + lane];
        float2 t3 = tmp[(size_t)q3.x * 32 + lane];
        float w0 = __int_as_float(q0.y), w1 = __int_as_float(q1.y);
        float w2 = __int_as_float(q2.y), w3 = __int_as_float(q3.y);
        a0 += t0.x * w0; a1 += t0.y * w0;
        a0 += t1.x * w1; a1 += t1.y * w1;
        a0 += t2.x * w2; a1 += t2.y * w2;
        a0 += t3.x * w3; a1 += t3.y * w3;
    }
    for (; e < e1; e++) {
        int2 q = g_sn[e];
        float2 t = tmp[(size_t)q.x * 32 + lane];
        float w = __int_as_float(q.y);
        a0 += t.x * w; a1 += t.y * w;
    }
    float2 bb = b1[lane];
    h[(size_t)i * 32 + lane] = make_float2(fmaxf(a0 + bb.x, 0.f),
                                           fmaxf(a1 + bb.y, 0.f));
}

// ---------------- aggregation, layer 2 (F=16): 16 threads per node, unroll 4 -
__global__ void k_agg2(const float* __restrict__ tmp,
                       const float* __restrict__ b2,
                       float* __restrict__ out, int n) {
    int i = (blockIdx.x * blockDim.x + threadIdx.x) >> 4;
    int l = threadIdx.x & 15;
    if (i >= n) return;
    float di = g_dinv[i];
    float a = tmp[(size_t)i * 16 + l] * di * di;

    int e1 = g_off[i];
    int e  = e1 - g_cnt[i];
    for (; e + 4 <= e1; e += 4) {
        int2 q0 = g_sn[e];
        int2 q1 = g_sn[e + 1];
        int2 q2 = g_sn[e + 2];
        int2 q3 = g_sn[e + 3];
        float t0 = tmp[(size_t)q0.x * 16 + l];
        float t1 = tmp[(size_t)q1.x * 16 + l];
        float t2 = tmp[(size_t)q2.x * 16 + l];
        float t3 = tmp[(size_t)q3.x * 16 + l];
        a += t0 * __int_as_float(q0.y);
        a += t1 * __int_as_float(q1.y);
        a += t2 * __int_as_float(q2.y);
        a += t3 * __int_as_float(q3.y);
    }
    for (; e < e1; e++) {
        int2 q = g_sn[e];
        a += tmp[(size_t)q.x * 16 + l] * __int_as_float(q.y);
    }
    out[(size_t)i * 16 + l] = a + b2[l];
}

// ---------------- launcher ---------------------------------------------------
extern "C" void kernel_launch(void* const* d_in, const int* in_sizes, int n_in,
                              void* d_out, int out_size) {
    const float* x  = (const float*)d_in[0];
    const void*  ei = d_in[1];
    const float* W1 = (const float*)d_in[2];
    const float* b1 = (const float*)d_in[3];
    const float* W2 = (const float*)d_in[4];
    const float* b2 = (const float*)d_in[5];
    float* out = (float*)d_out;

    const int n = in_sizes[0] / FH;
    const int E = in_sizes[1] / 2;

    float* tmp1; cudaGetSymbolAddress((void**)&tmp1, g_tmp1);
    float* h;    cudaGetSymbolAddress((void**)&h,    g_h);
    float* tmp2; cudaGetSymbolAddress((void**)&tmp2, g_tmp2);
    int*   cnt;  cudaGetSymbolAddress((void**)&cnt,  g_cnt);

    const int T  = 256;
    const int gE = (E + T - 1) / T;
    const int nb = (n + SCAN_T - 1) / SCAN_T;

    cudaMemsetAsync(cnt, 0, (size_t)(NN + 128) * sizeof(int));
    k_hist   <<<gE, T>>>(ei, E, n);
    k_scan   <<<nb, SCAN_T>>>(n);
    k_scatter<<<gE, T>>>(ei, E, n);

    // Layer 1
    k_gemm64<<<(n + 63) / 64, 128>>>(x, W1, tmp1, n);
    k_agg1  <<<(n * 32 + T - 1) / T, T>>>((const float2*)tmp1, (const float2*)b1,
                                          (float2*)h, n);
    // Layer 2
    k_gemm16<<<(n + 63) / 64, 64>>>(h, W2, tmp2, n);
    k_agg2  <<<(n * 16 + T - 1) / T, T>>>(tmp2, b2, out, n);

    (void)n_in; (void)out_size;
}